// round 1
// baseline (speedup 1.0000x reference)
#include <cuda_runtime.h>

#define Nn 8192
#define Cc 100
#define Dd 128
#define Hh 128
#define Oo 64
#define TPC 32                      // tokens per CTA chunk
#define MAXW (Cc + Nn / TPC)        // 356 worst-case work items

// ---- scratch (no allocations allowed) ----
__device__ int g_counts[Cc];
__device__ int g_cursor[Cc];
__device__ int g_perm[Nn];
__device__ int g_workCat[MAXW];
__device__ int g_workStart[MAXW];
__device__ int g_workCnt[MAXW];
__device__ int g_numWork;

__global__ void k_zero() {
    int i = threadIdx.x;
    if (i < Cc) g_counts[i] = 0;
}

__global__ void k_count(const int* __restrict__ cat) {
    int i = blockIdx.x * blockDim.x + threadIdx.x;
    if (i < Nn) atomicAdd(&g_counts[cat[i]], 1);
}

__global__ void k_scan() {
    __shared__ int cntS[Cc];
    __shared__ int off[Cc + 1];
    __shared__ int coff[Cc + 1];
    int t = threadIdx.x;
    if (t < Cc) cntS[t] = g_counts[t];
    __syncthreads();
    if (t == 0) {
        int r = 0, cr = 0;
        for (int i = 0; i < Cc; i++) {
            off[i] = r;  r += cntS[i];
            coff[i] = cr; cr += (cntS[i] + TPC - 1) / TPC;
        }
        off[Cc] = r; coff[Cc] = cr;
        g_numWork = cr;
    }
    __syncthreads();
    if (t < Cc) {
        g_cursor[t] = off[t];
        int nch = (cntS[t] + TPC - 1) / TPC;
        for (int j = 0; j < nch; j++) {
            int wi = coff[t] + j;
            g_workCat[wi]   = t;
            g_workStart[wi] = off[t] + j * TPC;
            int rem = cntS[t] - j * TPC;
            g_workCnt[wi]   = rem < TPC ? rem : TPC;
        }
    }
}

__global__ void k_scatter(const int* __restrict__ cat) {
    int i = blockIdx.x * blockDim.x + threadIdx.x;
    if (i < Nn) {
        int c = cat[i];
        int pos = atomicAdd(&g_cursor[c], 1);
        g_perm[pos] = i;
    }
}

// ---- main fused MLP kernel: one CTA = one (category, 32-token chunk) ----
// SMEM: W1 (64KB) + W2 (32KB) + x (16KB) + h (16KB) + biases + token ids
__global__ void __launch_bounds__(256, 1)
k_mlp(const float* __restrict__ x,
      const float* __restrict__ W1, const float* __restrict__ b1,
      const float* __restrict__ W2, const float* __restrict__ b2,
      float* __restrict__ out) {
    extern __shared__ float sm[];
    float* W1s = sm;                       // Dd*Hh      = 16384 f
    float* W2s = W1s + Dd * Hh;            // Hh*Oo      = 8192 f
    float* xs  = W2s + Hh * Oo;            // TPC*Dd     = 4096 f
    float* hs  = xs  + TPC * Dd;           // TPC*Hh     = 4096 f
    float* b1s = hs  + TPC * Hh;           // 128 f
    float* b2s = b1s + Hh;                 // 64 f
    int*   tok = (int*)(b2s + Oo);         // TPC ints

    int w = blockIdx.x;
    if (w >= g_numWork) return;
    int c     = g_workCat[w];
    int start = g_workStart[w];
    int cnt   = g_workCnt[w];

    int t = threadIdx.x;

    // stage weights (float4)
    const float4* W1g = (const float4*)(W1 + (size_t)c * Dd * Hh);
    float4* W1s4 = (float4*)W1s;
    #pragma unroll 4
    for (int i = t; i < Dd * Hh / 4; i += 256) W1s4[i] = W1g[i];
    const float4* W2g = (const float4*)(W2 + (size_t)c * Hh * Oo);
    float4* W2s4 = (float4*)W2s;
    #pragma unroll 2
    for (int i = t; i < Hh * Oo / 4; i += 256) W2s4[i] = W2g[i];
    if (t < Hh)  b1s[t] = b1[c * Hh + t];
    if (t < Oo)  b2s[t] = b2[c * Oo + t];
    if (t < TPC) tok[t] = (t < cnt) ? g_perm[start + t] : -1;
    __syncthreads();

    // stage x: 32 tokens * 32 float4 = 1024 float4
    float4* xs4 = (float4*)xs;
    #pragma unroll
    for (int i = t; i < TPC * Dd / 4; i += 256) {
        int lt = i >> 5;          // local token
        int q  = i & 31;          // float4 index within token
        int tk = tok[lt];
        xs4[i] = (tk >= 0) ? ((const float4*)(x + (size_t)tk * Dd))[q]
                           : make_float4(0.f, 0.f, 0.f, 0.f);
    }
    __syncthreads();

    int warp = t >> 5, lane = t & 31;
    int t0 = warp * 4;            // 8 warps x 4 tokens = 32 tokens

    // ---- layer 1: h[t][j] = relu(sum_d x[t][d] * W1[d][j] + b1[j]) ----
    // lane owns columns j = lane*4 .. lane*4+3 for 4 tokens -> 16 accumulators
    float a0x=0,a0y=0,a0z=0,a0w=0, a1x=0,a1y=0,a1z=0,a1w=0;
    float a2x=0,a2y=0,a2z=0,a2w=0, a3x=0,a3y=0,a3z=0,a3w=0;
    #pragma unroll 4
    for (int d = 0; d < Dd; d++) {
        float4 wv = W1s4[d * (Hh / 4) + lane];
        float x0 = xs[(t0 + 0) * Dd + d];
        float x1 = xs[(t0 + 1) * Dd + d];
        float x2 = xs[(t0 + 2) * Dd + d];
        float x3 = xs[(t0 + 3) * Dd + d];
        a0x += x0 * wv.x; a0y += x0 * wv.y; a0z += x0 * wv.z; a0w += x0 * wv.w;
        a1x += x1 * wv.x; a1y += x1 * wv.y; a1z += x1 * wv.z; a1w += x1 * wv.w;
        a2x += x2 * wv.x; a2y += x2 * wv.y; a2z += x2 * wv.z; a2w += x2 * wv.w;
        a3x += x3 * wv.x; a3y += x3 * wv.y; a3z += x3 * wv.z; a3w += x3 * wv.w;
    }
    {
        float4 bv = ((float4*)b1s)[lane];
        float4* h4 = (float4*)hs;
        float4 h0; h0.x = fmaxf(a0x + bv.x, 0.f); h0.y = fmaxf(a0y + bv.y, 0.f);
                   h0.z = fmaxf(a0z + bv.z, 0.f); h0.w = fmaxf(a0w + bv.w, 0.f);
        float4 h1; h1.x = fmaxf(a1x + bv.x, 0.f); h1.y = fmaxf(a1y + bv.y, 0.f);
                   h1.z = fmaxf(a1z + bv.z, 0.f); h1.w = fmaxf(a1w + bv.w, 0.f);
        float4 h2; h2.x = fmaxf(a2x + bv.x, 0.f); h2.y = fmaxf(a2y + bv.y, 0.f);
                   h2.z = fmaxf(a2z + bv.z, 0.f); h2.w = fmaxf(a2w + bv.w, 0.f);
        float4 h3; h3.x = fmaxf(a3x + bv.x, 0.f); h3.y = fmaxf(a3y + bv.y, 0.f);
                   h3.z = fmaxf(a3z + bv.z, 0.f); h3.w = fmaxf(a3w + bv.w, 0.f);
        h4[(t0 + 0) * (Hh / 4) + lane] = h0;
        h4[(t0 + 1) * (Hh / 4) + lane] = h1;
        h4[(t0 + 2) * (Hh / 4) + lane] = h2;
        h4[(t0 + 3) * (Hh / 4) + lane] = h3;
    }
    __syncwarp();

    // ---- layer 2: out[t][o] = sum_k h[t][k] * W2[k][o] + b2[o] ----
    // lane owns o = lane*2, lane*2+1 for 4 tokens -> 8 accumulators
    float c0x=0,c0y=0, c1x=0,c1y=0, c2x=0,c2y=0, c3x=0,c3y=0;
    float2* W2s2 = (float2*)W2s;
    #pragma unroll 4
    for (int k = 0; k < Hh; k++) {
        float2 wv = W2s2[k * (Oo / 2) + lane];
        float h0 = hs[(t0 + 0) * Hh + k];
        float h1 = hs[(t0 + 1) * Hh + k];
        float h2 = hs[(t0 + 2) * Hh + k];
        float h3 = hs[(t0 + 3) * Hh + k];
        c0x += h0 * wv.x; c0y += h0 * wv.y;
        c1x += h1 * wv.x; c1y += h1 * wv.y;
        c2x += h2 * wv.x; c2y += h2 * wv.y;
        c3x += h3 * wv.x; c3y += h3 * wv.y;
    }
    {
        float2 bv = ((float2*)b2s)[lane];
        #pragma unroll
        for (int tt = 0; tt < 4; tt++) {
            int tk = tok[t0 + tt];
            if (tk >= 0) {
                float2 o;
                float ax = (tt==0)?c0x:(tt==1)?c1x:(tt==2)?c2x:c3x;
                float ay = (tt==0)?c0y:(tt==1)?c1y:(tt==2)?c2y:c3y;
                o.x = ax + bv.x; o.y = ay + bv.y;
                ((float2*)(out + (size_t)tk * Oo))[lane] = o;
            }
        }
    }
}

extern "C" void kernel_launch(void* const* d_in, const int* in_sizes, int n_in,
                              void* d_out, int out_size) {
    const float* x   = (const float*)d_in[0];
    const int*   cat = (const int*)  d_in[1];
    const float* W1  = (const float*)d_in[2];
    const float* b1  = (const float*)d_in[3];
    const float* W2  = (const float*)d_in[4];
    const float* b2  = (const float*)d_in[5];
    float* out = (float*)d_out;

    static bool attr_set = false;
    size_t smem = (size_t)(Dd*Hh + Hh*Oo + TPC*Dd + TPC*Hh + Hh + Oo) * sizeof(float)
                + TPC * sizeof(int);
    if (!attr_set) {
        cudaFuncSetAttribute(k_mlp, cudaFuncAttributeMaxDynamicSharedMemorySize, (int)smem);
        attr_set = true;
    }

    k_zero<<<1, 128>>>();
    k_count<<<(Nn + 255) / 256, 256>>>(cat);
    k_scan<<<1, 128>>>();
    k_scatter<<<(Nn + 255) / 256, 256>>>(cat);
    k_mlp<<<MAXW, 256, smem>>>(x, W1, b1, W2, b2, out);
}

// round 2
// speedup vs baseline: 1.1969x; 1.1969x over previous
#include <cuda_runtime.h>

#define Nn 8192
#define Cc 100
#define Dd 128
#define Hh 128
#define Oo 64
#define TPC 48                 // tokens per CTA chunk
#define NPAIR (TPC / 2)        // 24 token pairs
#define XSTRIDE 260            // words per pair-row (128 f32x2 + 2 pad)
#define MAXW 384
#define NB 8
#define BT 1024

// ---------------- packed f32x2 helpers ----------------
#define FMA2(d, a, b) asm("fma.rn.f32x2 %0, %1, %2, %0;" : "+l"(d) : "l"(a), "l"(b))
#define DUP2(d, s)    asm("mov.b64 %0, {%1, %1};" : "=l"(d) : "f"(s))
#define PK2(d, lo, hi) asm("mov.b64 %0, {%1, %2};" : "=l"(d) : "f"(lo), "f"(hi))
#define UNPK2(lo, hi, s) asm("mov.b64 {%0, %1}, %2;" : "=f"(lo), "=f"(hi) : "l"(s))

// ---------------- scratch (no allocations allowed) ----------------
__device__ int g_bhist[NB * Cc];
__device__ int g_bbase[NB * Cc];
__device__ int g_perm[Nn];
__device__ int g_workCat[MAXW];
__device__ int g_workStart[MAXW];
__device__ int g_workCnt[MAXW];
__device__ int g_numWork;

// per-block histogram: SMEM atomics only
__global__ void k_hist(const int* __restrict__ cat) {
    __shared__ int h[Cc];
    int t = threadIdx.x, b = blockIdx.x;
    if (t < Cc) h[t] = 0;
    __syncthreads();
    atomicAdd(&h[cat[b * BT + t]], 1);
    __syncthreads();
    if (t < Cc) g_bhist[b * Cc + t] = h[t];
}

// scan: per-category offsets, per-block bases, chunk worklist
__global__ void k_scan() {
    __shared__ int tot[Cc];
    __shared__ int off[Cc];
    __shared__ int coff[Cc];
    int t = threadIdx.x;
    if (t < Cc) {
        int s = 0;
        #pragma unroll
        for (int b = 0; b < NB; b++) s += g_bhist[b * Cc + t];
        tot[t] = s;
    }
    __syncthreads();
    if (t == 0) {
        int r = 0, cr = 0;
        for (int c = 0; c < Cc; c++) {
            off[c] = r;  r += tot[c];
            coff[c] = cr; cr += (tot[c] + TPC - 1) / TPC;
        }
        g_numWork = cr;
    }
    __syncthreads();
    if (t < Cc) {
        int run = off[t];
        #pragma unroll
        for (int b = 0; b < NB; b++) {
            g_bbase[b * Cc + t] = run;
            run += g_bhist[b * Cc + t];
        }
        int nch = (tot[t] + TPC - 1) / TPC;
        for (int j = 0; j < nch; j++) {
            int wi = coff[t] + j;
            g_workCat[wi]   = t;
            g_workStart[wi] = off[t] + j * TPC;
            int rem = tot[t] - j * TPC;
            g_workCnt[wi]   = rem < TPC ? rem : TPC;
        }
    }
}

// scatter: SMEM cursor atomics only
__global__ void k_scatter(const int* __restrict__ cat) {
    __shared__ int cur[Cc];
    int t = threadIdx.x, b = blockIdx.x;
    if (t < Cc) cur[t] = g_bbase[b * Cc + t];
    __syncthreads();
    int id = b * BT + t;
    int pos = atomicAdd(&cur[cat[id]], 1);
    g_perm[pos] = id;
}

// ---------------- main fused MLP: one CTA = (category, 48-token chunk) ----------------
// 8 warps x 3 token-pairs (6 tokens) each. f32x2 packed along the token dimension.
__global__ void __launch_bounds__(256, 1)
k_mlp(const float* __restrict__ x,
      const float* __restrict__ W1, const float* __restrict__ b1,
      const float* __restrict__ W2, const float* __restrict__ b2,
      float* __restrict__ out) {
    extern __shared__ float sm[];
    float* W1s = sm;                      // 16384 f (64KB)  [d][h]
    float* W2s = W1s + Dd * Hh;           // 8192 f  (32KB)  [k][o]
    float* xp  = W2s + Hh * Oo;           // 24*260 = 6240 f : pair-major packed x
    float* hp  = xp + NPAIR * XSTRIDE;    // 6240 f : pair-major packed h
    float* b1s = hp + NPAIR * XSTRIDE;    // 128 f
    float* b2s = b1s + Hh;                // 64 f
    int*   tok = (int*)(b2s + Oo);        // 48 ints

    int w = blockIdx.x;
    if (w >= g_numWork) return;
    int c     = g_workCat[w];
    int start = g_workStart[w];
    int cnt   = g_workCnt[w];
    int t = threadIdx.x;

    // ---- stage weights + biases (coalesced float4) ----
    const float4* W1g = (const float4*)(W1 + (size_t)c * Dd * Hh);
    float4* W1s4 = (float4*)W1s;
    #pragma unroll 4
    for (int i = t; i < Dd * Hh / 4; i += 256) W1s4[i] = W1g[i];
    const float4* W2g = (const float4*)(W2 + (size_t)c * Hh * Oo);
    float4* W2s4 = (float4*)W2s;
    #pragma unroll 2
    for (int i = t; i < Hh * Oo / 4; i += 256) W2s4[i] = W2g[i];
    if (t < Hh)  b1s[t] = b1[c * Hh + t];
    if (t < Oo)  b2s[t] = b2[c * Oo + t];
    if (t < TPC) tok[t] = (t < cnt) ? g_perm[start + t] : -1;

    // ---- stage x transposed+pair-packed: xp[p][d] = (x_{2p}[d], x_{2p+1}[d]) ----
    #pragma unroll
    for (int i = t; i < NPAIR * 32; i += 256) {
        int p = i >> 5, q = i & 31;            // q indexes d-quads
        int iA = 2 * p, iB = 2 * p + 1;
        int tA = (iA < cnt) ? g_perm[start + iA] : -1;
        int tB = (iB < cnt) ? g_perm[start + iB] : -1;
        float4 a = (tA >= 0) ? ((const float4*)(x + (size_t)tA * Dd))[q]
                             : make_float4(0.f, 0.f, 0.f, 0.f);
        float4 bb = (tB >= 0) ? ((const float4*)(x + (size_t)tB * Dd))[q]
                              : make_float4(0.f, 0.f, 0.f, 0.f);
        float* dst = xp + (size_t)p * XSTRIDE + 8 * q;
        ((float4*)dst)[0] = make_float4(a.x, bb.x, a.y, bb.y);
        ((float4*)dst)[1] = make_float4(a.z, bb.z, a.w, bb.w);
    }
    __syncthreads();

    int warp = t >> 5, lane = t & 31;
    int p0 = warp * 3;                    // this warp's 3 pairs (6 tokens)
    if (warp * 6 >= cnt) return;          // remainder chunks: idle warps exit

    // ---- layer 1: 12 packed accumulators (3 pairs x 4 cols) ----
    unsigned long long acc[3][4];
    #pragma unroll
    for (int pp = 0; pp < 3; pp++)
        #pragma unroll
        for (int j = 0; j < 4; j++) acc[pp][j] = 0ULL;

    #pragma unroll 4
    for (int d = 0; d < Dd; d += 2) {
        ulonglong2 x0 = *(const ulonglong2*)(xp + (size_t)(p0 + 0) * XSTRIDE + 2 * d);
        ulonglong2 x1 = *(const ulonglong2*)(xp + (size_t)(p0 + 1) * XSTRIDE + 2 * d);
        ulonglong2 x2 = *(const ulonglong2*)(xp + (size_t)(p0 + 2) * XSTRIDE + 2 * d);
        float4 wa = W1s4[d * 32 + lane];
        float4 wb = W1s4[(d + 1) * 32 + lane];
        unsigned long long wa0, wa1, wa2, wa3, wb0, wb1, wb2, wb3;
        DUP2(wa0, wa.x); DUP2(wa1, wa.y); DUP2(wa2, wa.z); DUP2(wa3, wa.w);
        DUP2(wb0, wb.x); DUP2(wb1, wb.y); DUP2(wb2, wb.z); DUP2(wb3, wb.w);
        FMA2(acc[0][0], x0.x, wa0); FMA2(acc[0][1], x0.x, wa1);
        FMA2(acc[0][2], x0.x, wa2); FMA2(acc[0][3], x0.x, wa3);
        FMA2(acc[1][0], x1.x, wa0); FMA2(acc[1][1], x1.x, wa1);
        FMA2(acc[1][2], x1.x, wa2); FMA2(acc[1][3], x1.x, wa3);
        FMA2(acc[2][0], x2.x, wa0); FMA2(acc[2][1], x2.x, wa1);
        FMA2(acc[2][2], x2.x, wa2); FMA2(acc[2][3], x2.x, wa3);
        FMA2(acc[0][0], x0.y, wb0); FMA2(acc[0][1], x0.y, wb1);
        FMA2(acc[0][2], x0.y, wb2); FMA2(acc[0][3], x0.y, wb3);
        FMA2(acc[1][0], x1.y, wb0); FMA2(acc[1][1], x1.y, wb1);
        FMA2(acc[1][2], x1.y, wb2); FMA2(acc[1][3], x1.y, wb3);
        FMA2(acc[2][0], x2.y, wb0); FMA2(acc[2][1], x2.y, wb1);
        FMA2(acc[2][2], x2.y, wb2); FMA2(acc[2][3], x2.y, wb3);
    }

    // epilogue 1: bias + relu, store pair-packed h
    #pragma unroll
    for (int j = 0; j < 4; j++) {
        int col = 4 * lane + j;
        float bj = b1s[col];
        #pragma unroll
        for (int pp = 0; pp < 3; pp++) {
            float lo, hi;
            UNPK2(lo, hi, acc[pp][j]);
            lo = fmaxf(lo + bj, 0.f);
            hi = fmaxf(hi + bj, 0.f);
            unsigned long long v;
            PK2(v, lo, hi);
            *(unsigned long long*)(hp + (size_t)(p0 + pp) * XSTRIDE + 2 * col) = v;
        }
    }
    __syncwarp();

    // ---- layer 2: 6 packed accumulators (3 pairs x 2 cols) ----
    unsigned long long acc2[3][2];
    #pragma unroll
    for (int pp = 0; pp < 3; pp++) { acc2[pp][0] = 0ULL; acc2[pp][1] = 0ULL; }

    const float2* W2s2 = (const float2*)W2s;
    #pragma unroll 4
    for (int k = 0; k < Hh; k += 2) {
        ulonglong2 h0 = *(const ulonglong2*)(hp + (size_t)(p0 + 0) * XSTRIDE + 2 * k);
        ulonglong2 h1 = *(const ulonglong2*)(hp + (size_t)(p0 + 1) * XSTRIDE + 2 * k);
        ulonglong2 h2 = *(const ulonglong2*)(hp + (size_t)(p0 + 2) * XSTRIDE + 2 * k);
        float2 wA = W2s2[k * 32 + lane];
        float2 wB = W2s2[(k + 1) * 32 + lane];
        unsigned long long wA0, wA1, wB0, wB1;
        DUP2(wA0, wA.x); DUP2(wA1, wA.y);
        DUP2(wB0, wB.x); DUP2(wB1, wB.y);
        FMA2(acc2[0][0], h0.x, wA0); FMA2(acc2[0][1], h0.x, wA1);
        FMA2(acc2[1][0], h1.x, wA0); FMA2(acc2[1][1], h1.x, wA1);
        FMA2(acc2[2][0], h2.x, wA0); FMA2(acc2[2][1], h2.x, wA1);
        FMA2(acc2[0][0], h0.y, wB0); FMA2(acc2[0][1], h0.y, wB1);
        FMA2(acc2[1][0], h1.y, wB0); FMA2(acc2[1][1], h1.y, wB1);
        FMA2(acc2[2][0], h2.y, wB0); FMA2(acc2[2][1], h2.y, wB1);
    }

    // epilogue 2: bias + store (unpack token pairs)
    float b2x = b2s[2 * lane], b2y = b2s[2 * lane + 1];
    #pragma unroll
    for (int pp = 0; pp < 3; pp++) {
        int tA = tok[2 * (p0 + pp)];
        int tB = tok[2 * (p0 + pp) + 1];
        float a0lo, a0hi, a1lo, a1hi;
        UNPK2(a0lo, a0hi, acc2[pp][0]);
        UNPK2(a1lo, a1hi, acc2[pp][1]);
        if (tA >= 0) {
            float2 o; o.x = a0lo + b2x; o.y = a1lo + b2y;
            *(float2*)(out + (size_t)tA * Oo + 2 * lane) = o;
        }
        if (tB >= 0) {
            float2 o; o.x = a0hi + b2x; o.y = a1hi + b2y;
            *(float2*)(out + (size_t)tB * Oo + 2 * lane) = o;
        }
    }
}

extern "C" void kernel_launch(void* const* d_in, const int* in_sizes, int n_in,
                              void* d_out, int out_size) {
    const float* x   = (const float*)d_in[0];
    const int*   cat = (const int*)  d_in[1];
    const float* W1  = (const float*)d_in[2];
    const float* b1  = (const float*)d_in[3];
    const float* W2  = (const float*)d_in[4];
    const float* b2  = (const float*)d_in[5];
    float* out = (float*)d_out;

    size_t smem = (size_t)(Dd * Hh + Hh * Oo + 2 * NPAIR * XSTRIDE + Hh + Oo) * sizeof(float)
                + TPC * sizeof(int);
    static bool attr_set = false;
    if (!attr_set) {
        cudaFuncSetAttribute(k_mlp, cudaFuncAttributeMaxDynamicSharedMemorySize, (int)smem);
        attr_set = true;
    }

    k_hist<<<NB, BT>>>(cat);
    k_scan<<<1, 128>>>();
    k_scatter<<<NB, BT>>>(cat);
    k_mlp<<<MAXW, 256, smem>>>(x, W1, b1, W2, b2, out);
}

// round 3
// speedup vs baseline: 1.3762x; 1.1498x over previous
#include <cuda_runtime.h>

#define Nn 8192
#define Cc 100
#define Dd 128
#define Hh 128
#define Oo 64
#define TPC 32                 // tokens per CTA chunk
#define NPAIR (TPC / 2)        // 16 token pairs
#define XSTRIDE 256            // words per pair-row (128 f32x2)
#define MAXW 356
#define NB 8
#define BT 1024

// ---------------- packed f32x2 helpers ----------------
#define FMA2(d, a, b) asm("fma.rn.f32x2 %0, %1, %2, %0;" : "+l"(d) : "l"(a), "l"(b))
#define DUP2(d, s)    asm("mov.b64 %0, {%1, %1};" : "=l"(d) : "f"(s))
#define PK2(d, lo, hi) asm("mov.b64 %0, {%1, %2};" : "=l"(d) : "f"(lo), "f"(hi))
#define UNPK2(lo, hi, s) asm("mov.b64 {%0, %1}, %2;" : "=f"(lo), "=f"(hi) : "l"(s))

// ---------------- scratch (no allocations allowed) ----------------
__device__ int g_bhist[NB * Cc];
__device__ int g_bbase[NB * Cc];
__device__ int g_perm[Nn];
__device__ int g_workCat[MAXW];
__device__ int g_workStart[MAXW];
__device__ int g_workCnt[MAXW];
__device__ int g_numWork;

// per-block histogram: SMEM atomics only
__global__ void k_hist(const int* __restrict__ cat) {
    __shared__ int h[Cc];
    int t = threadIdx.x, b = blockIdx.x;
    if (t < Cc) h[t] = 0;
    __syncthreads();
    atomicAdd(&h[cat[b * BT + t]], 1);
    __syncthreads();
    if (t < Cc) g_bhist[b * Cc + t] = h[t];
}

// scan: per-category offsets, per-block bases, chunk worklist
__global__ void k_scan() {
    __shared__ int tot[Cc];
    __shared__ int off[Cc];
    __shared__ int coff[Cc];
    int t = threadIdx.x;
    if (t < Cc) {
        int s = 0;
        #pragma unroll
        for (int b = 0; b < NB; b++) s += g_bhist[b * Cc + t];
        tot[t] = s;
    }
    __syncthreads();
    if (t == 0) {
        int r = 0, cr = 0;
        for (int c = 0; c < Cc; c++) {
            off[c] = r;  r += tot[c];
            coff[c] = cr; cr += (tot[c] + TPC - 1) / TPC;
        }
        g_numWork = cr;
    }
    __syncthreads();
    if (t < Cc) {
        int run = off[t];
        #pragma unroll
        for (int b = 0; b < NB; b++) {
            g_bbase[b * Cc + t] = run;
            run += g_bhist[b * Cc + t];
        }
        int nch = (tot[t] + TPC - 1) / TPC;
        for (int j = 0; j < nch; j++) {
            int wi = coff[t] + j;
            g_workCat[wi]   = t;
            g_workStart[wi] = off[t] + j * TPC;
            int rem = tot[t] - j * TPC;
            g_workCnt[wi]   = rem < TPC ? rem : TPC;
        }
    }
}

// scatter: SMEM cursor atomics only
__global__ void k_scatter(const int* __restrict__ cat) {
    __shared__ int cur[Cc];
    int t = threadIdx.x, b = blockIdx.x;
    if (t < Cc) cur[t] = g_bbase[b * Cc + t];
    __syncthreads();
    int id = b * BT + t;
    int pos = atomicAdd(&cur[cat[id]], 1);
    g_perm[pos] = id;
}

// ---------------- main fused MLP: one CTA = (category, 32-token chunk) ----------------
// 8 warps x 2 token-pairs (4 tokens) each. f32x2 packed along the token dimension.
// SMEM = W1 (64KB) + W2 (32KB) + xp (16KB) = 112KB -> 2 CTAs/SM.
// h overwrites xp in place (warp-private rows).
__global__ void __launch_bounds__(256, 2)
k_mlp(const float* __restrict__ x,
      const float* __restrict__ W1, const float* __restrict__ b1,
      const float* __restrict__ W2, const float* __restrict__ b2,
      float* __restrict__ out) {
    extern __shared__ float sm[];
    float* W1s = sm;                      // 16384 f (64KB)  [d][h]
    float* W2s = W1s + Dd * Hh;           // 8192 f  (32KB)  [k][o]
    float* xp  = W2s + Hh * Oo;           // 16*256 = 4096 f : pair-major packed x / h

    int w = blockIdx.x;
    if (w >= g_numWork) return;
    int c     = g_workCat[w];
    int start = g_workStart[w];
    int cnt   = g_workCnt[w];
    int t = threadIdx.x;

    // ---- stage weights (coalesced float4) ----
    const float4* W1g = (const float4*)(W1 + (size_t)c * Dd * Hh);
    float4* W1s4 = (float4*)W1s;
    #pragma unroll 4
    for (int i = t; i < Dd * Hh / 4; i += 256) W1s4[i] = W1g[i];
    const float4* W2g = (const float4*)(W2 + (size_t)c * Hh * Oo);
    float4* W2s4 = (float4*)W2s;
    #pragma unroll 2
    for (int i = t; i < Hh * Oo / 4; i += 256) W2s4[i] = W2g[i];

    // ---- stage x transposed+pair-packed: xp[p][d] = (x_{2p}[d], x_{2p+1}[d]) ----
    #pragma unroll
    for (int i = t; i < NPAIR * 32; i += 256) {
        int p = i >> 5, q = i & 31;            // q indexes d-quads
        int iA = 2 * p, iB = 2 * p + 1;
        int tA = (iA < cnt) ? g_perm[start + iA] : -1;
        int tB = (iB < cnt) ? g_perm[start + iB] : -1;
        float4 a = (tA >= 0) ? ((const float4*)(x + (size_t)tA * Dd))[q]
                             : make_float4(0.f, 0.f, 0.f, 0.f);
        float4 bb = (tB >= 0) ? ((const float4*)(x + (size_t)tB * Dd))[q]
                              : make_float4(0.f, 0.f, 0.f, 0.f);
        float* dst = xp + (size_t)p * XSTRIDE + 8 * q;
        ((float4*)dst)[0] = make_float4(a.x, bb.x, a.y, bb.y);
        ((float4*)dst)[1] = make_float4(a.z, bb.z, a.w, bb.w);
    }
    __syncthreads();

    int warp = t >> 5, lane = t & 31;
    int p0 = warp * 2;                    // this warp's 2 pairs (4 tokens)
    if (warp * 4 >= cnt) return;          // remainder chunks: idle warps exit

    // ---- layer 1: 8 packed accumulators (2 pairs x 4 cols) ----
    unsigned long long acc[2][4];
    #pragma unroll
    for (int pp = 0; pp < 2; pp++)
        #pragma unroll
        for (int j = 0; j < 4; j++) acc[pp][j] = 0ULL;

    #pragma unroll 4
    for (int d = 0; d < Dd; d += 2) {
        ulonglong2 x0 = *(const ulonglong2*)(xp + (size_t)(p0 + 0) * XSTRIDE + 2 * d);
        ulonglong2 x1 = *(const ulonglong2*)(xp + (size_t)(p0 + 1) * XSTRIDE + 2 * d);
        float4 wa = W1s4[d * 32 + lane];
        float4 wb = W1s4[(d + 1) * 32 + lane];
        unsigned long long wa0, wa1, wa2, wa3, wb0, wb1, wb2, wb3;
        DUP2(wa0, wa.x); DUP2(wa1, wa.y); DUP2(wa2, wa.z); DUP2(wa3, wa.w);
        DUP2(wb0, wb.x); DUP2(wb1, wb.y); DUP2(wb2, wb.z); DUP2(wb3, wb.w);
        FMA2(acc[0][0], x0.x, wa0); FMA2(acc[0][1], x0.x, wa1);
        FMA2(acc[0][2], x0.x, wa2); FMA2(acc[0][3], x0.x, wa3);
        FMA2(acc[1][0], x1.x, wa0); FMA2(acc[1][1], x1.x, wa1);
        FMA2(acc[1][2], x1.x, wa2); FMA2(acc[1][3], x1.x, wa3);
        FMA2(acc[0][0], x0.y, wb0); FMA2(acc[0][1], x0.y, wb1);
        FMA2(acc[0][2], x0.y, wb2); FMA2(acc[0][3], x0.y, wb3);
        FMA2(acc[1][0], x1.y, wb0); FMA2(acc[1][1], x1.y, wb1);
        FMA2(acc[1][2], x1.y, wb2); FMA2(acc[1][3], x1.y, wb3);
    }

    // epilogue 1: bias (from global, L2-hot) + relu, store pair-packed h in place over xp
    {
        float4 bv = *(const float4*)(b1 + (size_t)c * Hh + 4 * lane);
        float bj[4] = {bv.x, bv.y, bv.z, bv.w};
        #pragma unroll
        for (int j = 0; j < 4; j++) {
            int col = 4 * lane + j;
            #pragma unroll
            for (int pp = 0; pp < 2; pp++) {
                float lo, hi;
                UNPK2(lo, hi, acc[pp][j]);
                lo = fmaxf(lo + bj[j], 0.f);
                hi = fmaxf(hi + bj[j], 0.f);
                unsigned long long v;
                PK2(v, lo, hi);
                *(unsigned long long*)(xp + (size_t)(p0 + pp) * XSTRIDE + 2 * col) = v;
            }
        }
    }
    __syncwarp();

    // ---- layer 2: 4 packed accumulators (2 pairs x 2 cols) ----
    unsigned long long acc2[2][2];
    acc2[0][0] = acc2[0][1] = acc2[1][0] = acc2[1][1] = 0ULL;

    const float2* W2s2 = (const float2*)W2s;
    #pragma unroll 4
    for (int k = 0; k < Hh; k += 2) {
        ulonglong2 h0 = *(const ulonglong2*)(xp + (size_t)(p0 + 0) * XSTRIDE + 2 * k);
        ulonglong2 h1 = *(const ulonglong2*)(xp + (size_t)(p0 + 1) * XSTRIDE + 2 * k);
        float2 wA = W2s2[k * 32 + lane];
        float2 wB = W2s2[(k + 1) * 32 + lane];
        unsigned long long wA0, wA1, wB0, wB1;
        DUP2(wA0, wA.x); DUP2(wA1, wA.y);
        DUP2(wB0, wB.x); DUP2(wB1, wB.y);
        FMA2(acc2[0][0], h0.x, wA0); FMA2(acc2[0][1], h0.x, wA1);
        FMA2(acc2[1][0], h1.x, wA0); FMA2(acc2[1][1], h1.x, wA1);
        FMA2(acc2[0][0], h0.y, wB0); FMA2(acc2[0][1], h0.y, wB1);
        FMA2(acc2[1][0], h1.y, wB0); FMA2(acc2[1][1], h1.y, wB1);
    }

    // epilogue 2: bias + store (unpack token pairs)
    {
        float2 b2v = *(const float2*)(b2 + (size_t)c * Oo + 2 * lane);
        #pragma unroll
        for (int pp = 0; pp < 2; pp++) {
            int iA = 2 * (p0 + pp), iB = 2 * (p0 + pp) + 1;
            int tA = (iA < cnt) ? g_perm[start + iA] : -1;
            int tB = (iB < cnt) ? g_perm[start + iB] : -1;
            float a0lo, a0hi, a1lo, a1hi;
            UNPK2(a0lo, a0hi, acc2[pp][0]);
            UNPK2(a1lo, a1hi, acc2[pp][1]);
            if (tA >= 0) {
                float2 o; o.x = a0lo + b2v.x; o.y = a1lo + b2v.y;
                *(float2*)(out + (size_t)tA * Oo + 2 * lane) = o;
            }
            if (tB >= 0) {
                float2 o; o.x = a0hi + b2v.x; o.y = a1hi + b2v.y;
                *(float2*)(out + (size_t)tB * Oo + 2 * lane) = o;
            }
        }
    }
}

extern "C" void kernel_launch(void* const* d_in, const int* in_sizes, int n_in,
                              void* d_out, int out_size) {
    const float* x   = (const float*)d_in[0];
    const int*   cat = (const int*)  d_in[1];
    const float* W1  = (const float*)d_in[2];
    const float* b1  = (const float*)d_in[3];
    const float* W2  = (const float*)d_in[4];
    const float* b2  = (const float*)d_in[5];
    float* out = (float*)d_out;

    size_t smem = (size_t)(Dd * Hh + Hh * Oo + NPAIR * XSTRIDE) * sizeof(float); // 114688 B
    static bool attr_set = false;
    if (!attr_set) {
        cudaFuncSetAttribute(k_mlp, cudaFuncAttributeMaxDynamicSharedMemorySize, (int)smem);
        attr_set = true;
    }

    k_hist<<<NB, BT>>>(cat);
    k_scan<<<1, 128>>>();
    k_scatter<<<NB, BT>>>(cat);
    k_mlp<<<MAXW, 256, smem>>>(x, W1, b1, W2, b2, out);
}